// round 10
// baseline (speedup 1.0000x reference)
#include <cuda_runtime.h>

#define BB 4
#define TT 32
#define DD 256
#define NN 1024
#define GROUP 32      // CTAs per batch group
#define COLS 32       // G columns owned per CTA
#define NTHR 512      // threads in main kernel (16 warps)
#define CPW 2         // columns per warp (register-resident)

// ---------------- device scratch ----------------
__device__ float    g_xn[BB*TT*NN];      // relu(ln(x@E))
__device__ float    g_tn[BB*TT*NN];      // relu(ln(targets@E))
__device__ float    g_p[2][BB][NN];      // p1 / p2 exchange buffers
__device__ float    g_reason[BB*TT*NN];  // max(p1,p2,p3)
__device__ unsigned g_flag[2][BB][64];   // data-ready flags: [phase][batch][part(<32), padded]

// ---------------- sync primitives ----------------
__device__ __forceinline__ void st_release(unsigned* p, unsigned v) {
  asm volatile("st.release.gpu.global.u32 [%0], %1;" :: "l"(p), "r"(v) : "memory");
}
__device__ __forceinline__ unsigned ld_acquire(const unsigned* p) {
  unsigned v;
  asm volatile("ld.acquire.gpu.global.u32 %0, [%1];" : "=r"(v) : "l"(p) : "memory");
  return v;
}

// ---------------- kernel 1: neurons = relu(layernorm(X @ E)) ----------------
// 1024 threads, 1 column per thread, grid = 128 rows.
__global__ void __launch_bounds__(1024) prep_kernel(const float* __restrict__ x_seq,
                                                    const float* __restrict__ targets,
                                                    const float* __restrict__ E) {
  __shared__ float xs[DD], ts[DD];
  __shared__ float2 red[32];
  int row = blockIdx.x;            // b*TT + t
  int tid = threadIdx.x;           // column 0..1023
  int w = tid >> 5, l = tid & 31;

  if (row == 0 && tid < 2*BB*64)   // reset flags for this launch
    ((unsigned*)g_flag)[tid] = 0u;

  if (tid < DD) {
    xs[tid] = x_seq[row*DD + tid];
    ts[tid] = targets[row*DD + tid];
  }
  __syncthreads();

  float ax = 0.f, at = 0.f;
#pragma unroll 8
  for (int k = 0; k < DD; ++k) {
    float e = __ldg(E + k*NN + tid);
    ax += xs[k]*e;
    at += ts[k]*e;
  }

  // --- layernorm+relu for x ---
  {
    float s1 = ax, s2 = ax*ax;
#pragma unroll
    for (int o = 16; o; o >>= 1) {
      s1 += __shfl_xor_sync(0xffffffffu, s1, o);
      s2 += __shfl_xor_sync(0xffffffffu, s2, o);
    }
    if (l == 0) { red[w].x = s1; red[w].y = s2; }
    __syncthreads();
    float t1 = 0.f, t2 = 0.f;
#pragma unroll
    for (int i = 0; i < 32; ++i) { t1 += red[i].x; t2 += red[i].y; }
    float mu  = t1 * (1.0f/NN);
    float inv = rsqrtf(t2*(1.0f/NN) - mu*mu + 1e-5f);
    g_xn[row*NN + tid] = fmaxf(0.f, (ax - mu)*inv);
  }
  __syncthreads();   // red[] reuse
  // --- layernorm+relu for targets ---
  {
    float s1 = at, s2 = at*at;
#pragma unroll
    for (int o = 16; o; o >>= 1) {
      s1 += __shfl_xor_sync(0xffffffffu, s1, o);
      s2 += __shfl_xor_sync(0xffffffffu, s2, o);
    }
    if (l == 0) { red[w].x = s1; red[w].y = s2; }
    __syncthreads();
    float t1 = 0.f, t2 = 0.f;
#pragma unroll
    for (int i = 0; i < 32; ++i) { t1 += red[i].x; t2 += red[i].y; }
    float mu  = t1 * (1.0f/NN);
    float inv = rsqrtf(t2*(1.0f/NN) - mu*mu + 1e-5f);
    g_tn[row*NN + tid] = fmaxf(0.f, (at - mu)*inv);
  }
}

// ---------------- kernel 2: persistent scan, register-resident G ----------
// CTA (b, part) owns G[:, part*32 .. +31]. 16 warps x 2 cols each.
// Thread (w, l): cols cbase = part*32 + w*2 + {0,1}, rows n = l + 32*j.
__global__ void __launch_bounds__(NTHR, 1) main_kernel() {
  __shared__ float xb[2*NN];       // ping-pong x_neuron vectors

  int cta  = blockIdx.x;
  int b    = cta >> 5;
  int part = cta & 31;
  int tid = threadIdx.x, w = tid >> 5, l = tid & 31;
  int cbase = part*COLS + w*CPW;

  float gr0[32], gr1[32];
#pragma unroll
  for (int j = 0; j < 32; ++j) {
    int n = l + 32*j;
    gr0[j] = (n == cbase)     ? 0.01f : 0.0f;
    gr1[j] = (n == cbase + 1) ? 0.01f : 0.0f;
  }

  // stage step-0 inputs
  {
    const float* gx = g_xn + (b*TT)*NN;
    for (int i = tid; i < NN; i += NTHR) xb[i] = gx[i];
  }
  float tvc0 = 0.5f * g_tn[(b*TT)*NN + cbase];
  float tvc1 = 0.5f * g_tn[(b*TT)*NN + cbase + 1];
  __syncthreads();

  for (int t = 0; t < TT; ++t) {
    const float* xc = xb + (t & 1)*NN;
    const float* xp = xb + ((t & 1)^1)*NN;

    float acc0 = 0.f, acc1 = 0.f;

    // ---- phase 1: apply pending rank-1 max-update (t>0), compute p1 ----
    if (t > 0) {
#pragma unroll
      for (int j = 0; j < 32; ++j) {
        float xpv = xp[l + 32*j];
        float xcv = xc[l + 32*j];
        gr0[j] = fmaxf(gr0[j], xpv*tvc0);
        gr1[j] = fmaxf(gr1[j], xpv*tvc1);
        acc0 += xcv*gr0[j];
        acc1 += xcv*gr1[j];
      }
    } else {
#pragma unroll
      for (int j = 0; j < 32; ++j) {
        float xcv = xc[l + 32*j];
        acc0 += xcv*gr0[j];
        acc1 += xcv*gr1[j];
      }
    }
#pragma unroll
    for (int o = 16; o; o >>= 1) {
      acc0 += __shfl_xor_sync(0xffffffffu, acc0, o);
      acc1 += __shfl_xor_sync(0xffffffffu, acc1, o);
    }
    if (l == 0) {
      float2 st; st.x = acc0; st.y = acc1;
      *(float2*)(&g_p[0][b][cbase]) = st;
    }
    float r0 = acc0, r1 = acc1;

    // publish p1 chunk
    __syncthreads();
    if (tid == 0) st_release(&g_flag[0][b][part], (unsigned)(2*t + 1));

    // prefetch next-step inputs in the poll shadow
    float tvn0 = tvc0, tvn1 = tvc1;
    if (t + 1 < TT) {
      const float* gx2 = g_xn + (b*TT + t + 1)*NN;
      float* xn2 = xb + ((t + 1) & 1)*NN;
      for (int i = tid; i < NN; i += NTHR) xn2[i] = gx2[i];
      tvn0 = 0.5f * g_tn[(b*TT + t + 1)*NN + cbase];
      tvn1 = 0.5f * g_tn[(b*TT + t + 1)*NN + cbase + 1];
    }

    // wait for all parts' p1 (warp 0 only; lane l watches part l)
    if (w == 0) {
      unsigned tok = (unsigned)(2*t + 1);
      const unsigned* fp = &g_flag[0][b][l];
      unsigned ready = 0;
      do {
        if (!ready) ready = (ld_acquire(fp) >= tok);
      } while (!__all_sync(0xffffffffu, ready));
    }
    __syncthreads();

    // ---- phase 2: p2 = p1 . G  (direct L2 reads, no staging) ----
    acc0 = 0.f; acc1 = 0.f;
    {
      const float* gp = &g_p[0][b][0];
      float pv[16];
#pragma unroll
      for (int bat = 0; bat < 2; ++bat) {
#pragma unroll
        for (int j = 0; j < 16; ++j) pv[j] = __ldcg(gp + l + 32*(bat*16 + j));
#pragma unroll
        for (int j = 0; j < 16; ++j) {
          acc0 += pv[j]*gr0[bat*16 + j];
          acc1 += pv[j]*gr1[bat*16 + j];
        }
      }
    }
#pragma unroll
    for (int o = 16; o; o >>= 1) {
      acc0 += __shfl_xor_sync(0xffffffffu, acc0, o);
      acc1 += __shfl_xor_sync(0xffffffffu, acc1, o);
    }
    if (l == 0) {
      float2 st; st.x = acc0; st.y = acc1;
      *(float2*)(&g_p[1][b][cbase]) = st;
    }
    r0 = fmaxf(r0, acc0); r1 = fmaxf(r1, acc1);

    // publish p2 chunk
    __syncthreads();
    if (tid == 0) st_release(&g_flag[1][b][part], (unsigned)(2*t + 2));

    if (w == 0) {
      unsigned tok = (unsigned)(2*t + 2);
      const unsigned* fp = &g_flag[1][b][l];
      unsigned ready = 0;
      do {
        if (!ready) ready = (ld_acquire(fp) >= tok);
      } while (!__all_sync(0xffffffffu, ready));
    }
    __syncthreads();

    // ---- phase 3: p3 = p2 . G ----
    acc0 = 0.f; acc1 = 0.f;
    {
      const float* gp = &g_p[1][b][0];
      float pv[16];
#pragma unroll
      for (int bat = 0; bat < 2; ++bat) {
#pragma unroll
        for (int j = 0; j < 16; ++j) pv[j] = __ldcg(gp + l + 32*(bat*16 + j));
#pragma unroll
        for (int j = 0; j < 16; ++j) {
          acc0 += pv[j]*gr0[bat*16 + j];
          acc1 += pv[j]*gr1[bat*16 + j];
        }
      }
    }
#pragma unroll
    for (int o = 16; o; o >>= 1) {
      acc0 += __shfl_xor_sync(0xffffffffu, acc0, o);
      acc1 += __shfl_xor_sync(0xffffffffu, acc1, o);
    }
    r0 = fmaxf(r0, acc0); r1 = fmaxf(r1, acc1);

    if (l == 0) {
      float2 st; st.x = r0; st.y = r1;
      *(float2*)(&g_reason[(b*TT + t)*NN + cbase]) = st;
    }
    tvc0 = tvn0; tvc1 = tvn1;
    // next iteration's xb half already staged; syncs above ordered it
  }
}

// ---------------- kernel 3: y = relu(reasoning @ Dy) ----------------
__global__ void __launch_bounds__(256) out_kernel(const float* __restrict__ Dy,
                                                  float* __restrict__ out) {
  __shared__ float rs[4*NN];
  int rbase = blockIdx.x * 4;      // grid 32 -> 128 rows
  int tid = threadIdx.x;
  int c4 = tid & 63;               // float4 column group
  int r  = tid >> 6;               // row within block (0..3)
  for (int i = tid; i < 4*NN; i += 256) rs[i] = g_reason[rbase*NN + i];
  __syncthreads();

  const float4* Dy4 = (const float4*)Dy;  // [1024][64] float4
  const float* rr = rs + r*NN;
  float4 a = make_float4(0.f,0.f,0.f,0.f);
#pragma unroll 8
  for (int n = 0; n < NN; ++n) {
    float4 d = Dy4[n*64 + c4];
    float pv = rr[n];
    a.x += pv*d.x; a.y += pv*d.y; a.z += pv*d.z; a.w += pv*d.w;
  }
  float4 o;
  o.x = fmaxf(a.x,0.f); o.y = fmaxf(a.y,0.f);
  o.z = fmaxf(a.z,0.f); o.w = fmaxf(a.w,0.f);
  ((float4*)(out + (rbase + r)*DD))[c4] = o;
}

// ---------------- launch ----------------
extern "C" void kernel_launch(void* const* d_in, const int* in_sizes, int n_in,
                              void* d_out, int out_size) {
  const float* x_seq   = (const float*)d_in[0];  // [4,32,256]
  const float* targets = (const float*)d_in[1];  // [4,32,256]
  const float* E       = (const float*)d_in[2];  // [256,1024]
  const float* Dy      = (const float*)d_in[3];  // [1024,256]
  float* out = (float*)d_out;                    // [4,32,256]

  prep_kernel<<<BB*TT, 1024>>>(x_seq, targets, E);   // also resets flags
  main_kernel<<<BB*GROUP, NTHR>>>();
  out_kernel<<<32, 256>>>(Dy, out);
}

// round 11
// speedup vs baseline: 1.6767x; 1.6767x over previous
#include <cuda_runtime.h>

#define BB 4
#define TT 32
#define DD 256
#define NN 1024
#define GROUP 32      // CTAs per batch group
#define COLS 32       // G columns owned per CTA
#define NTHR 512      // threads in main kernel (16 warps)
#define CPW 2         // columns per warp (register-resident)

// ---------------- device scratch ----------------
__device__ float    g_xn[BB*TT*NN];      // relu(ln(x@E))
__device__ float    g_tn[BB*TT*NN];      // relu(ln(targets@E))
__device__ float    g_p[2][BB][NN];      // p1 / p2 exchange buffers
__device__ float    g_reason[BB*TT*NN];  // max(p1,p2,p3)
__device__ unsigned g_bar[BB*32];        // padded barrier counter per group

// ---------------- sync primitives ----------------
__device__ __forceinline__ void bar_arrive(unsigned* p) {
  asm volatile("red.release.gpu.global.add.u32 [%0], %1;" :: "l"(p), "r"(1u) : "memory");
}
__device__ __forceinline__ unsigned bar_poll(const unsigned* p) {
  unsigned v;
  asm volatile("ld.acquire.gpu.global.u32 %0, [%1];" : "=r"(v) : "l"(p) : "memory");
  return v;
}

// ---------------- kernel 1: neurons = relu(layernorm(X @ E)) ----------------
// 1024 threads, 1 column per thread, grid = 128 rows.
__global__ void __launch_bounds__(1024) prep_kernel(const float* __restrict__ x_seq,
                                                    const float* __restrict__ targets,
                                                    const float* __restrict__ E) {
  __shared__ float xs[DD], ts[DD];
  __shared__ float2 red[32];
  int row = blockIdx.x;            // b*TT + t
  int tid = threadIdx.x;           // column 0..1023
  int w = tid >> 5, l = tid & 31;

  if (row == 0 && tid < BB) g_bar[tid * 32] = 0u;   // reset group barriers

  if (tid < DD) {
    xs[tid] = x_seq[row*DD + tid];
    ts[tid] = targets[row*DD + tid];
  }
  __syncthreads();

  float ax = 0.f, at = 0.f;
#pragma unroll 8
  for (int k = 0; k < DD; ++k) {
    float e = __ldg(E + k*NN + tid);
    ax += xs[k]*e;
    at += ts[k]*e;
  }

  // --- layernorm+relu for x ---
  {
    float s1 = ax, s2 = ax*ax;
#pragma unroll
    for (int o = 16; o; o >>= 1) {
      s1 += __shfl_xor_sync(0xffffffffu, s1, o);
      s2 += __shfl_xor_sync(0xffffffffu, s2, o);
    }
    if (l == 0) { red[w].x = s1; red[w].y = s2; }
    __syncthreads();
    float t1 = 0.f, t2 = 0.f;
#pragma unroll
    for (int i = 0; i < 32; ++i) { t1 += red[i].x; t2 += red[i].y; }
    float mu  = t1 * (1.0f/NN);
    float inv = rsqrtf(t2*(1.0f/NN) - mu*mu + 1e-5f);
    g_xn[row*NN + tid] = fmaxf(0.f, (ax - mu)*inv);
  }
  __syncthreads();   // red[] reuse
  // --- layernorm+relu for targets ---
  {
    float s1 = at, s2 = at*at;
#pragma unroll
    for (int o = 16; o; o >>= 1) {
      s1 += __shfl_xor_sync(0xffffffffu, s1, o);
      s2 += __shfl_xor_sync(0xffffffffu, s2, o);
    }
    if (l == 0) { red[w].x = s1; red[w].y = s2; }
    __syncthreads();
    float t1 = 0.f, t2 = 0.f;
#pragma unroll
    for (int i = 0; i < 32; ++i) { t1 += red[i].x; t2 += red[i].y; }
    float mu  = t1 * (1.0f/NN);
    float inv = rsqrtf(t2*(1.0f/NN) - mu*mu + 1e-5f);
    g_tn[row*NN + tid] = fmaxf(0.f, (at - mu)*inv);
  }
}

// ---------------- kernel 2: persistent scan, register-resident G ----------
// CTA (b, part) owns G[:, part*32 .. +31]. 16 warps x 2 cols each.
// Thread (w, l): cols cbase = part*32 + w*2 + {0,1}, rows n = l + 32*j.
__global__ void __launch_bounds__(NTHR, 1) main_kernel() {
  __shared__ float xb[2*NN];       // ping-pong x_neuron vectors
  __shared__ float pb[NN];         // staged p vector
  __shared__ float tb[2][COLS];    // ping-pong 0.5*tn values

  int cta  = blockIdx.x;
  int b    = cta >> 5;
  int part = cta & 31;
  int mbase = part * COLS;
  int tid = threadIdx.x, w = tid >> 5, l = tid & 31;
  unsigned* barp = g_bar + b*32;
  int cbase = mbase + w*CPW;

  float gr0[32], gr1[32];
#pragma unroll
  for (int j = 0; j < 32; ++j) {
    int n = l + 32*j;
    gr0[j] = (n == cbase)     ? 0.01f : 0.0f;
    gr1[j] = (n == cbase + 1) ? 0.01f : 0.0f;
  }

  // stage step-0 inputs
  {
    const float* gx = g_xn + (b*TT)*NN;
    for (int i = tid; i < NN; i += NTHR) xb[i] = gx[i];
    if (tid < COLS) tb[0][tid] = 0.5f * g_tn[(b*TT)*NN + mbase + tid];
  }
  __syncthreads();

  unsigned epoch = 0;

  for (int t = 0; t < TT; ++t) {
    const float* xc = xb + (t & 1)*NN;
    const float* xp = xb + ((t & 1)^1)*NN;
    float tv0 = tb[t & 1][w*CPW + 0];
    float tv1 = tb[t & 1][w*CPW + 1];

    float acc0 = 0.f, acc1 = 0.f;
    float r0, r1;

    // ---- phase 1: apply pending rank-1 max-update (t>0), compute p1 ----
    if (t > 0) {
#pragma unroll
      for (int j = 0; j < 32; ++j) {
        float xpv = xp[l + 32*j];
        float xcv = xc[l + 32*j];
        gr0[j] = fmaxf(gr0[j], xpv*tv0);
        gr1[j] = fmaxf(gr1[j], xpv*tv1);
        acc0 += xcv*gr0[j];
        acc1 += xcv*gr1[j];
      }
    } else {
#pragma unroll
      for (int j = 0; j < 32; ++j) {
        float xcv = xc[l + 32*j];
        acc0 += xcv*gr0[j];
        acc1 += xcv*gr1[j];
      }
    }
#pragma unroll
    for (int o = 16; o; o >>= 1) {
      acc0 += __shfl_xor_sync(0xffffffffu, acc0, o);
      acc1 += __shfl_xor_sync(0xffffffffu, acc1, o);
    }
    if (l == 0) {
      float2 st; st.x = acc0; st.y = acc1;
      *(float2*)(&g_p[0][b][cbase]) = st;
    }
    r0 = acc0; r1 = acc1;

    // ---- group barrier #1 (prefetch next-step inputs in wait shadow) ----
    epoch++;
    __syncthreads();
    if (tid == 0) bar_arrive(barp);
    if (t + 1 < TT) {
      const float* gx2 = g_xn + (b*TT + t + 1)*NN;
      float* xn2 = xb + ((t + 1) & 1)*NN;
      for (int i = tid; i < NN; i += NTHR) xn2[i] = gx2[i];
      if (tid < COLS)
        tb[(t + 1) & 1][tid] = 0.5f * g_tn[(b*TT + t + 1)*NN + mbase + tid];
    }
    if (tid == 0) {
      unsigned tgt = epoch * GROUP;
      while (bar_poll(barp) < tgt) { }
    }
    __syncthreads();
    {
      const float2* gp2 = (const float2*)&g_p[0][b][0];
      ((float2*)pb)[tid] = __ldcg(gp2 + tid);   // NN/2 == NTHR
    }
    __syncthreads();

    // ---- phase 2: p2 = p1 . G ----
    acc0 = 0.f; acc1 = 0.f;
#pragma unroll
    for (int j = 0; j < 32; ++j) {
      float pv = pb[l + 32*j];
      acc0 += pv*gr0[j];
      acc1 += pv*gr1[j];
    }
#pragma unroll
    for (int o = 16; o; o >>= 1) {
      acc0 += __shfl_xor_sync(0xffffffffu, acc0, o);
      acc1 += __shfl_xor_sync(0xffffffffu, acc1, o);
    }
    if (l == 0) {
      float2 st; st.x = acc0; st.y = acc1;
      *(float2*)(&g_p[1][b][cbase]) = st;
    }
    r0 = fmaxf(r0, acc0); r1 = fmaxf(r1, acc1);

    // ---- group barrier #2 ----
    epoch++;
    __syncthreads();
    if (tid == 0) {
      bar_arrive(barp);
      unsigned tgt = epoch * GROUP;
      while (bar_poll(barp) < tgt) { }
    }
    __syncthreads();
    {
      const float2* gp2 = (const float2*)&g_p[1][b][0];
      ((float2*)pb)[tid] = __ldcg(gp2 + tid);
    }
    __syncthreads();

    // ---- phase 3: p3 = p2 . G (column-local) ----
    acc0 = 0.f; acc1 = 0.f;
#pragma unroll
    for (int j = 0; j < 32; ++j) {
      float pv = pb[l + 32*j];
      acc0 += pv*gr0[j];
      acc1 += pv*gr1[j];
    }
#pragma unroll
    for (int o = 16; o; o >>= 1) {
      acc0 += __shfl_xor_sync(0xffffffffu, acc0, o);
      acc1 += __shfl_xor_sync(0xffffffffu, acc1, o);
    }
    r0 = fmaxf(r0, acc0); r1 = fmaxf(r1, acc1);

    if (l == 0) {
      float2 st; st.x = r0; st.y = r1;
      *(float2*)(&g_reason[(b*TT + t)*NN + cbase]) = st;
    }
    // next iteration's xb half already staged; barrier-#1 sync ordered it
  }
}

// ---------------- kernel 3: y = relu(reasoning @ Dy) ----------------
__global__ void __launch_bounds__(256) out_kernel(const float* __restrict__ Dy,
                                                  float* __restrict__ out) {
  __shared__ float rs[4*NN];
  int rbase = blockIdx.x * 4;      // grid 32 -> 128 rows
  int tid = threadIdx.x;
  int c4 = tid & 63;               // float4 column group
  int r  = tid >> 6;               // row within block (0..3)
  for (int i = tid; i < 4*NN; i += 256) rs[i] = g_reason[rbase*NN + i];
  __syncthreads();

  const float4* Dy4 = (const float4*)Dy;  // [1024][64] float4
  const float* rr = rs + r*NN;
  float4 a = make_float4(0.f,0.f,0.f,0.f);
#pragma unroll 8
  for (int n = 0; n < NN; ++n) {
    float4 d = Dy4[n*64 + c4];
    float pv = rr[n];
    a.x += pv*d.x; a.y += pv*d.y; a.z += pv*d.z; a.w += pv*d.w;
  }
  float4 o;
  o.x = fmaxf(a.x,0.f); o.y = fmaxf(a.y,0.f);
  o.z = fmaxf(a.z,0.f); o.w = fmaxf(a.w,0.f);
  ((float4*)(out + (rbase + r)*DD))[c4] = o;
}

// ---------------- launch ----------------
extern "C" void kernel_launch(void* const* d_in, const int* in_sizes, int n_in,
                              void* d_out, int out_size) {
  const float* x_seq   = (const float*)d_in[0];  // [4,32,256]
  const float* targets = (const float*)d_in[1];  // [4,32,256]
  const float* E       = (const float*)d_in[2];  // [256,1024]
  const float* Dy      = (const float*)d_in[3];  // [1024,256]
  float* out = (float*)d_out;                    // [4,32,256]

  prep_kernel<<<BB*TT, 1024>>>(x_seq, targets, E);   // also resets barriers
  main_kernel<<<BB*GROUP, NTHR>>>();
  out_kernel<<<32, 256>>>(Dy, out);
}